// round 5
// baseline (speedup 1.0000x reference)
#include <cuda_runtime.h>
#include <cuda_bf16.h>
#include <math.h>
#include <float.h>
#include <stdint.h>

#define Nn 15000
#define Ee 60000
#define Bb 512
#define Dd 64
#define EHh 128
#define DDf 4096   // D*D
#define NSTEPS 6

// ---------------- device scratch (static globals; no allocations) ----------------
static __device__ __nv_bfloat16 g_Hb[(size_t)Ee * EHh];   // edge hidden  [E,128] bf16
static __device__ __nv_bfloat16 g_W2b[(size_t)DDf * EHh]; // en_w2 bf16   [4096,128]
static __device__ __nv_bfloat16 g_ewb[(size_t)Ee * DDf];  // edge weights [E,4096] bf16 492MB
static __device__ float g_h[Nn * Dd];              // node state (h == out)
static __device__ float g_agg[Nn * Dd];            // message aggregate (atomics)
static __device__ float g_invdeg[Nn];
static __device__ int   g_degi[Nn];
static __device__ float g_wihT[Dd * 192];          // GRU W_ih transposed [64][192]
static __device__ float g_whhT[Dd * 192];          // GRU W_hh transposed [64][192]
static __device__ int   g_boff[Bb + 1];            // batch segment offsets

// ---------------- small helpers ----------------
__device__ __forceinline__ float sigm(float x) { return 1.0f / (1.0f + expf(-x)); }

__device__ __forceinline__ void ldsm_x4(uint32_t* r, const void* p) {
    uint32_t addr = (uint32_t)__cvta_generic_to_shared(p);
    asm volatile("ldmatrix.sync.aligned.m8n8.x4.shared.b16 {%0,%1,%2,%3}, [%4];"
                 : "=r"(r[0]), "=r"(r[1]), "=r"(r[2]), "=r"(r[3]) : "r"(addr));
}
__device__ __forceinline__ void ldsm_x2(uint32_t* r, const void* p) {
    uint32_t addr = (uint32_t)__cvta_generic_to_shared(p);
    asm volatile("ldmatrix.sync.aligned.m8n8.x2.shared.b16 {%0,%1}, [%2];"
                 : "=r"(r[0]), "=r"(r[1]) : "r"(addr));
}
__device__ __forceinline__ void mma_bf16(float* c, const uint32_t* a, const uint32_t* b) {
    asm volatile(
        "mma.sync.aligned.m16n8k16.row.col.f32.bf16.bf16.f32 "
        "{%0,%1,%2,%3}, {%4,%5,%6,%7}, {%8,%9}, {%0,%1,%2,%3};"
        : "+f"(c[0]), "+f"(c[1]), "+f"(c[2]), "+f"(c[3])
        : "r"(a[0]), "r"(a[1]), "r"(a[2]), "r"(a[3]), "r"(b[0]), "r"(b[1]));
}
__device__ __forceinline__ void cp_async16(void* dst, const void* src, int sz) {
    uint32_t d = (uint32_t)__cvta_generic_to_shared(dst);
    asm volatile("cp.async.cg.shared.global [%0], [%1], 16, %2;"
                 :: "r"(d), "l"(src), "r"(sz));
}
__device__ __forceinline__ void cp_commit() {
    asm volatile("cp.async.commit_group;");
}
template <int N>
__device__ __forceinline__ void cp_wait() {
    asm volatile("cp.async.wait_group %0;" :: "n"(N));
}

// ---------------- prep kernels (fused so msg step1 is launch #4) ----------------
// prep_small: lin0 + zero g_agg + zero g_degi
#define PS_LIN0 (Nn * Dd)
#define PS_AGG  (Nn * Dd)
#define PS_TOT  (PS_LIN0 + PS_AGG + Nn)
__global__ void prep_small_kernel(const float* __restrict__ x,
                                  const float* __restrict__ w,
                                  const float* __restrict__ bvec) {
    int idx = blockIdx.x * blockDim.x + threadIdx.x;
    if (idx < PS_LIN0) {
        int n = idx >> 6, o = idx & 63;
        float acc = bvec[o];
        const float* xr = x + n * 15;
        const float* wr = w + o * 15;
#pragma unroll
        for (int j = 0; j < 15; j++) acc = fmaf(xr[j], wr[j], acc);
        g_h[idx] = fmaxf(acc, 0.0f);
    } else if (idx < PS_LIN0 + PS_AGG) {
        g_agg[idx - PS_LIN0] = 0.0f;
    } else if (idx < PS_TOT) {
        g_degi[idx - PS_LIN0 - PS_AGG] = 0;
    }
}

// prep_edges: convert_w2 + ehid (both feed the GEMM)
#define PE_W2 (DDf * EHh)
#define PE_EH (Ee * EHh)
__global__ void prep_edges_kernel(const float* __restrict__ w2,
                                  const float* __restrict__ ea,
                                  const float* __restrict__ w1,
                                  const float* __restrict__ b1) {
    int idx = blockIdx.x * blockDim.x + threadIdx.x;
    if (idx < PE_W2) {
        g_W2b[idx] = __float2bfloat16_rn(w2[idx]);
    } else if (idx < PE_W2 + PE_EH) {
        int t = idx - PE_W2;
        int e = t >> 7, k = t & 127;
        float acc = b1[k];
        const float* er = ea + e * 5;
        const float* wr = w1 + k * 5;
#pragma unroll
        for (int j = 0; j < 5; j++) acc = fmaf(er[j], wr[j], acc);
        g_Hb[t] = __float2bfloat16_rn(fmaxf(acc, 0.0f));
    }
}

__global__ void boff_kernel(const int* __restrict__ batch) {
    int b = blockIdx.x * blockDim.x + threadIdx.x;
    if (b > Bb) return;
    int lo = 0, hi = Nn;
    while (lo < hi) {
        int mid = (lo + hi) >> 1;
        if (batch[mid] < b) lo = mid + 1; else hi = mid;
    }
    g_boff[b] = lo;
}

__global__ void deg_kernel(const int* __restrict__ edge_index) {
    int e = blockIdx.x * blockDim.x + threadIdx.x;
    if (e < Ee) atomicAdd(&g_degi[edge_index[Ee + e]], 1);
}

__global__ void invdeg_kernel() {
    int n = blockIdx.x * blockDim.x + threadIdx.x;
    if (n < Nn) g_invdeg[n] = 1.0f / fmaxf((float)g_degi[n], 1.0f);
}

__global__ void transpose_gru_kernel(const float* __restrict__ wih,
                                     const float* __restrict__ whh) {
    int idx = blockIdx.x * blockDim.x + threadIdx.x;
    if (idx >= 192 * 64) return;
    int o = idx / 64, i = idx % 64;
    g_wihT[i * 192 + o] = wih[o * 64 + i];
    g_whhT[i * 192 + o] = whh[o * 64 + i];
}

// ---------------- ew GEMM: single-shot full-K tiles (unchanged from R4) ---------
#define SPAD 136
__global__ void __launch_bounds__(256) gemm_ew_mma(const float* __restrict__ b2) {
    extern __shared__ __align__(16) __nv_bfloat16 smem[];
    __nv_bfloat16* As = smem;                 // [128][136]
    __nv_bfloat16* Bs = smem + 128 * SPAD;    // [128][136]

    const int bm = blockIdx.y;
    const int bn = blockIdx.x;
    const int tid = threadIdx.x;
    const int warp = tid >> 5, lane = tid & 31;
    const int wm = (warp >> 2) * 64;
    const int wn = (warp & 3) * 32;

#pragma unroll
    for (int u = tid; u < 2048; u += 256) {
        int r = u >> 4, c = (u & 15) * 8;
        int grow = bm * 128 + r;
        cp_async16(&As[r * SPAD + c], &g_Hb[(size_t)grow * 128 + c],
                   (grow < Ee) ? 16 : 0);
        cp_async16(&Bs[r * SPAD + c], &g_W2b[(size_t)(bn * 128 + r) * 128 + c], 16);
    }
    cp_commit();
    cp_wait<0>();
    __syncthreads();

    float acc[4][4][4];
#pragma unroll
    for (int mi = 0; mi < 4; mi++)
#pragma unroll
        for (int ni = 0; ni < 4; ni++)
#pragma unroll
            for (int r = 0; r < 4; r++) acc[mi][ni][r] = 0.0f;

    const int lrow = lane & 15;
    const int lcol8 = ((lane >> 4) & 1) * 8;
    const int lbrow = lane & 7;
    const int lbcol8 = ((lane >> 3) & 1) * 8;

#pragma unroll
    for (int k0 = 0; k0 < 128; k0 += 16) {
        uint32_t a[4][4], b[4][2];
#pragma unroll
        for (int mi = 0; mi < 4; mi++)
            ldsm_x4(a[mi], &As[(wm + mi * 16 + lrow) * SPAD + k0 + lcol8]);
#pragma unroll
        for (int ni = 0; ni < 4; ni++)
            ldsm_x2(b[ni], &Bs[(wn + ni * 8 + lbrow) * SPAD + k0 + lbcol8]);
#pragma unroll
        for (int mi = 0; mi < 4; mi++)
#pragma unroll
            for (int ni = 0; ni < 4; ni++)
                mma_bf16(acc[mi][ni], a[mi], b[ni]);
    }
    __syncthreads();

    __nv_bfloat16* stage = As;
    const int r0 = lane >> 2;
    const int c0 = (lane & 3) * 2;
#pragma unroll
    for (int mi = 0; mi < 4; mi++) {
#pragma unroll
        for (int ni = 0; ni < 4; ni++) {
            int cl = wn + ni * 8 + c0;
            float bb0 = b2[bn * 128 + cl], bb1 = b2[bn * 128 + cl + 1];
            int rl = wm + mi * 16 + r0;
            __nv_bfloat162 v;
            v.x = __float2bfloat16_rn(acc[mi][ni][0] + bb0);
            v.y = __float2bfloat16_rn(acc[mi][ni][1] + bb1);
            *(__nv_bfloat162*)&stage[rl * SPAD + cl] = v;
            v.x = __float2bfloat16_rn(acc[mi][ni][2] + bb0);
            v.y = __float2bfloat16_rn(acc[mi][ni][3] + bb1);
            *(__nv_bfloat162*)&stage[(rl + 8) * SPAD + cl] = v;
        }
    }
    __syncthreads();
#pragma unroll
    for (int p = 0; p < 8; p++) {
        int idx = tid + p * 256;
        int row = idx >> 4, c8 = (idx & 15) * 8;
        int grow = bm * 128 + row;
        if (grow < Ee)
            *(uint4*)&g_ewb[(size_t)grow * DDf + bn * 128 + c8] =
                *(const uint4*)&stage[row * SPAD + c8];
    }
}

// ---------------- msg v4: cp.async bulk-streamed, edge-parallel, atomics --------
// Block: 256 threads, 32 edges in 4 chunks of 8, double-buffered 64KB smem bufs.
// cp.async keeps ~64-128KB in flight per SM -> DRAM-saturated streaming of ew.
// Each warp computes one edge's 64x64 matvec from smem, scatter via atomicAdd.
#define MSG_SMEM (2 * 65536 + 32 * 64 * 4)   // 139264 B
__global__ void __launch_bounds__(256) msg_cp_kernel(const int* __restrict__ edge_index) {
    extern __shared__ __align__(16) unsigned char sm[];
    float* xs = (float*)(sm + 2 * 65536);     // [32][64]
    const int tid = threadIdx.x;
    const int warp = tid >> 5, lane = tid & 31;
    const int base = blockIdx.x * 32;

    // gather source-node features for all 32 edges (plain loads, 8KB)
    for (int u = tid; u < 32 * 64; u += 256) {
        int le = u >> 6, d = u & 63;
        int e = base + le;
        xs[u] = (e < Ee) ? g_h[edge_index[e] * 64 + d] : 0.0f;
    }

    // issue cp.async for one 8-edge chunk into buffer buf
    auto load_chunk = [&](int k, int buf) {
        unsigned char* dst0 = sm + buf * 65536;
#pragma unroll
        for (int u = tid; u < 4096; u += 256) {
            int le = u >> 9;                  // edge within chunk (512 x 16B per edge)
            int off = (u & 511) * 16;         // byte offset within edge row block
            int e = base + k * 8 + le;
            const unsigned char* src =
                (const unsigned char*)g_ewb + ((size_t)e * DDf) * 2 + off;
            cp_async16(dst0 + le * 8192 + off, src, (e < Ee) ? 16 : 0);
        }
        cp_commit();
    };

    load_chunk(0, 0);
    load_chunk(1, 1);

    const int r = lane >> 3, c8 = (lane & 7) * 8;
    const unsigned FULL = 0xffffffffu;

#pragma unroll
    for (int k = 0; k < 4; k++) {
        if (k < 3) cp_wait<1>(); else cp_wait<0>();
        __syncthreads();
        const int buf = k & 1;
        const int le32 = k * 8 + warp;
        const int e = base + le32;
        if (e < Ee) {
            const __nv_bfloat16* wp =
                (const __nv_bfloat16*)(sm + buf * 65536 + warp * 8192) + c8;
            const float* xv = xs + le32 * 64;
            float acc[8];
#pragma unroll
            for (int j = 0; j < 8; j++) acc[j] = 0.0f;
#pragma unroll
            for (int t = 0; t < 16; t++) {
                int i = t * 4 + r;
                uint4 v = *(const uint4*)(wp + i * 64);
                float xi = xv[i];
                const __nv_bfloat162* p = (const __nv_bfloat162*)&v;
                acc[0] = fmaf(xi, __bfloat162float(p[0].x), acc[0]);
                acc[1] = fmaf(xi, __bfloat162float(p[0].y), acc[1]);
                acc[2] = fmaf(xi, __bfloat162float(p[1].x), acc[2]);
                acc[3] = fmaf(xi, __bfloat162float(p[1].y), acc[3]);
                acc[4] = fmaf(xi, __bfloat162float(p[2].x), acc[4]);
                acc[5] = fmaf(xi, __bfloat162float(p[2].y), acc[5]);
                acc[6] = fmaf(xi, __bfloat162float(p[3].x), acc[6]);
                acc[7] = fmaf(xi, __bfloat162float(p[3].y), acc[7]);
            }
#pragma unroll
            for (int j = 0; j < 8; j++) {
                acc[j] += __shfl_xor_sync(FULL, acc[j], 8);
                acc[j] += __shfl_xor_sync(FULL, acc[j], 16);
            }
            if (lane < 8) {
                int tgt = edge_index[Ee + e];
                float* dst = g_agg + tgt * 64 + lane * 8;
#pragma unroll
                for (int j = 0; j < 8; j++) atomicAdd(dst + j, acc[j]);
            }
        }
        __syncthreads();
        if (k + 2 < 4) load_chunk(k + 2, k & 1);
    }
}

// ---------------- per-step GRU node kernel (re-zeros g_agg for next step) -------
__global__ void __launch_bounds__(192) gru_kernel(const float* __restrict__ conv_b,
                                                  const float* __restrict__ b_ih,
                                                  const float* __restrict__ b_hh) {
    __shared__ float ms[16][64];
    __shared__ float hs[16][64];
    __shared__ float gis[16][192];
    __shared__ float ghs[16][192];
    const int nb = blockIdx.x * 16;
    const int tid = threadIdx.x;

    for (int idx = tid; idx < 16 * 64; idx += 192) {
        int n = idx >> 6, i = idx & 63;
        int gn = nb + n;
        if (gn < Nn) {
            float a = g_agg[gn * 64 + i];
            ms[n][i] = fmaxf(fmaf(a, g_invdeg[gn], conv_b[i]), 0.0f);
            hs[n][i] = g_h[gn * 64 + i];
            g_agg[gn * 64 + i] = 0.0f;   // re-zero for next step's atomics
        } else {
            ms[n][i] = 0.0f; hs[n][i] = 0.0f;
        }
    }
    __syncthreads();

    const int o = tid;
    float ai[16], ah[16];
#pragma unroll
    for (int n = 0; n < 16; n++) { ai[n] = 0.0f; ah[n] = 0.0f; }
#pragma unroll 8
    for (int i = 0; i < 64; i++) {
        float wi = g_wihT[i * 192 + o];
        float wh = g_whhT[i * 192 + o];
#pragma unroll
        for (int n = 0; n < 16; n++) {
            ai[n] = fmaf(ms[n][i], wi, ai[n]);
            ah[n] = fmaf(hs[n][i], wh, ah[n]);
        }
    }
    float bi = b_ih[o], bh = b_hh[o];
#pragma unroll
    for (int n = 0; n < 16; n++) { gis[n][o] = ai[n] + bi; ghs[n][o] = ah[n] + bh; }
    __syncthreads();

    for (int idx = tid; idx < 16 * 64; idx += 192) {
        int n = idx >> 6, d = idx & 63;
        int gn = nb + n;
        if (gn >= Nn) continue;
        float rg = sigm(gis[n][d] + ghs[n][d]);
        float zg = sigm(gis[n][64 + d] + ghs[n][64 + d]);
        float ng = tanhf(fmaf(rg, ghs[n][128 + d], gis[n][128 + d]));
        float hv = hs[n][d];
        g_h[gn * 64 + d] = (1.0f - zg) * ng + zg * hv;
    }
}

// ---------------- fused Set2Set (6 steps) + output MLP, one block per graph -----
__global__ void __launch_bounds__(256) set2set_kernel(
    const float* __restrict__ w_ih, const float* __restrict__ w_hh,
    const float* __restrict__ b_ih, const float* __restrict__ b_hh,
    const float* __restrict__ lin1_w, const float* __restrict__ lin1_b,
    const float* __restrict__ lin2_w, const float* __restrict__ lin2_b,
    float* __restrict__ out) {
    const int b = blockIdx.x;
    const int tid = threadIdx.x;
    const int lane = tid & 31, w = tid >> 5;
    __shared__ float q[128], hl[64], cl[64], g[256];
    __shared__ float red[8];
    __shared__ float rpart[8][64];
    __shared__ float emax_s, denom_s;
    __shared__ float z[64];

    if (tid < 128) q[tid] = 0.0f;
    if (tid < 64) { hl[tid] = 0.0f; cl[tid] = 0.0f; }
    __syncthreads();

    const int s = g_boff[b], epos = g_boff[b + 1];
    const unsigned FULL = 0xffffffffu;

    for (int step = 0; step < NSTEPS; step++) {
        {
            int j = tid;
            float acc = b_ih[j] + b_hh[j];
            const float* wr = w_ih + j * 128;
#pragma unroll 8
            for (int k = 0; k < 128; k++) acc = fmaf(q[k], wr[k], acc);
            const float* wr2 = w_hh + j * 64;
#pragma unroll 8
            for (int k = 0; k < 64; k++) acc = fmaf(hl[k], wr2[k], acc);
            g[j] = acc;
        }
        __syncthreads();
        if (tid < 64) {
            int d = tid;
            float ig = g[d], fg = g[64 + d], gg = g[128 + d], og = g[192 + d];
            float c = sigm(fg) * cl[d] + sigm(ig) * tanhf(gg);
            cl[d] = c;
            hl[d] = sigm(og) * tanhf(c);
        }
        __syncthreads();

        float lmax = -FLT_MAX;
        for (int n = s + w; n < epos; n += 8) {
            const float* hr = g_h + n * 64;
            float v = hr[lane] * hl[lane] + hr[32 + lane] * hl[32 + lane];
#pragma unroll
            for (int off = 16; off > 0; off >>= 1) v += __shfl_down_sync(FULL, v, off);
            v = __shfl_sync(FULL, v, 0);
            lmax = fmaxf(lmax, v);
        }
        if (lane == 0) red[w] = lmax;
        __syncthreads();
        if (tid == 0) {
            float m = red[0];
#pragma unroll
            for (int i = 1; i < 8; i++) m = fmaxf(m, red[i]);
            emax_s = m;
        }
        __syncthreads();
        float emax = emax_s;

        float lsum = 0.0f, r0 = 0.0f, r1 = 0.0f;
        for (int n = s + w; n < epos; n += 8) {
            const float* hr = g_h + n * 64;
            float x0 = hr[lane], x1 = hr[32 + lane];
            float v = x0 * hl[lane] + x1 * hl[32 + lane];
#pragma unroll
            for (int off = 16; off > 0; off >>= 1) v += __shfl_down_sync(FULL, v, off);
            v = __shfl_sync(FULL, v, 0);
            float ex = expf(v - emax);
            lsum += ex;
            r0 = fmaf(ex, x0, r0);
            r1 = fmaf(ex, x1, r1);
        }
        if (lane == 0) red[w] = lsum;
        rpart[w][lane] = r0;
        rpart[w][32 + lane] = r1;
        __syncthreads();
        if (tid == 0) {
            float ssum = 0.0f;
#pragma unroll
            for (int i = 0; i < 8; i++) ssum += red[i];
            denom_s = ssum;
        }
        __syncthreads();
        if (tid < 64) {
            float rv = 0.0f;
#pragma unroll
            for (int i = 0; i < 8; i++) rv += rpart[i][tid];
            q[64 + tid] = rv / (denom_s + 1e-16f);
            q[tid] = hl[tid];
        }
        __syncthreads();
    }

    if (tid < 64) {
        float acc = lin1_b[tid];
        const float* wr = lin1_w + tid * 128;
#pragma unroll 8
        for (int k = 0; k < 128; k++) acc = fmaf(q[k], wr[k], acc);
        z[tid] = fmaxf(acc, 0.0f);
    }
    __syncthreads();
    if (tid < 12) {
        float acc = lin2_b[tid];
        const float* wr = lin2_w + tid * 64;
#pragma unroll
        for (int d = 0; d < 64; d++) acc = fmaf(z[d], wr[d], acc);
        out[b * 12 + tid] = acc;
    }
}

// ---------------- launch ----------------
extern "C" void kernel_launch(void* const* d_in, const int* in_sizes, int n_in,
                              void* d_out, int out_size) {
    const float* x         = (const float*)d_in[0];
    const float* edge_attr = (const float*)d_in[1];
    const int*   edge_index= (const int*)  d_in[2];
    const int*   batch     = (const int*)  d_in[3];
    const float* lin0_w    = (const float*)d_in[4];
    const float* lin0_b    = (const float*)d_in[5];
    const float* en_w1     = (const float*)d_in[6];
    const float* en_b1     = (const float*)d_in[7];
    const float* en_w2     = (const float*)d_in[8];
    const float* en_b2     = (const float*)d_in[9];
    const float* conv_b    = (const float*)d_in[10];
    const float* gru_w_ih  = (const float*)d_in[11];
    const float* gru_w_hh  = (const float*)d_in[12];
    const float* gru_b_ih  = (const float*)d_in[13];
    const float* gru_b_hh  = (const float*)d_in[14];
    const float* lstm_w_ih = (const float*)d_in[15];
    const float* lstm_w_hh = (const float*)d_in[16];
    const float* lstm_b_ih = (const float*)d_in[17];
    const float* lstm_b_hh = (const float*)d_in[18];
    const float* lin1_w    = (const float*)d_in[19];
    const float* lin1_b    = (const float*)d_in[20];
    const float* lin2_w    = (const float*)d_in[21];
    const float* lin2_b    = (const float*)d_in[22];
    float* out = (float*)d_out;

    const int gemm_smem = 2 * 128 * SPAD * (int)sizeof(__nv_bfloat16);  // 69632
    cudaFuncSetAttribute(gemm_ew_mma, cudaFuncAttributeMaxDynamicSharedMemorySize,
                         gemm_smem);
    cudaFuncSetAttribute(msg_cp_kernel, cudaFuncAttributeMaxDynamicSharedMemorySize,
                         MSG_SMEM);

    // 1: prep_small (lin0 + zero agg/degi)
    prep_small_kernel<<<(PS_TOT + 255) / 256, 256>>>(x, lin0_w, lin0_b);
    // 2: prep_edges (w2->bf16 + edge hidden)
    prep_edges_kernel<<<(PE_W2 + PE_EH + 255) / 256, 256>>>(en_w2, edge_attr, en_w1, en_b1);
    // 3: GEMM
    dim3 gemm_grid(DDf / 128, (Ee + 127) / 128);
    gemm_ew_mma<<<gemm_grid, 256, gemm_smem>>>(en_b2);
    // 4: msg step 1  (ncu samples this launch index)
    msg_cp_kernel<<<(Ee + 31) / 32, 256, MSG_SMEM>>>(edge_index);

    deg_kernel<<<(Ee + 255) / 256, 256>>>(edge_index);
    invdeg_kernel<<<(Nn + 255) / 256, 256>>>();
    transpose_gru_kernel<<<(192 * 64 + 255) / 256, 256>>>(gru_w_ih, gru_w_hh);
    gru_kernel<<<(Nn + 15) / 16, 192>>>(conv_b, gru_b_ih, gru_b_hh);

    for (int s = 1; s < NSTEPS; s++) {
        msg_cp_kernel<<<(Ee + 31) / 32, 256, MSG_SMEM>>>(edge_index);
        gru_kernel<<<(Nn + 15) / 16, 192>>>(conv_b, gru_b_ih, gru_b_hh);
    }

    boff_kernel<<<3, 256>>>(batch);
    set2set_kernel<<<Bb, 256>>>(lstm_w_ih, lstm_w_hh, lstm_b_ih, lstm_b_hh,
                                lin1_w, lin1_b, lin2_w, lin2_b, out);
}

// round 6
// speedup vs baseline: 1.2663x; 1.2663x over previous
#include <cuda_runtime.h>
#include <cuda_bf16.h>
#include <math.h>
#include <float.h>
#include <stdint.h>

#define Nn 15000
#define Ee 60000
#define Bb 512
#define Dd 64
#define EHh 128
#define DDf 4096   // D*D
#define NSTEPS 6

// ---------------- device scratch (static globals; no allocations) ----------------
static __device__ __nv_bfloat16 g_Hb[(size_t)Ee * EHh];    // edge hidden [E,128]
static __device__ __nv_bfloat16 g_W2b[(size_t)DDf * EHh];  // en_w2 bf16 [4096,128]
static __device__ __nv_bfloat16 g_ewb[(size_t)Ee * DDf];   // edge weights [E,4096] bf16
static __device__ float g_h[Nn * Dd];                      // node state fp32 (master)
static __device__ __nv_bfloat16 g_mh[Nn * 128];            // [m | h] per node, bf16
static __device__ float g_gates[(size_t)Nn * 384];         // GEMM out: gi(192)|gh(192)
static __device__ __nv_bfloat16 g_WcatT[384 * 128];        // block-diag GRU weights^T
static __device__ float g_invdeg[Nn];
static __device__ int   g_degi[Nn];
static __device__ int   g_eoff[Nn + 1];                    // CSR offsets by target
static __device__ int   g_perm[Ee];                        // edge ids grouped by target
static __device__ int   g_boff[Bb + 1];                    // batch segment offsets

// ---------------- small helpers ----------------
__device__ __forceinline__ float sigm(float x) { return 1.0f / (1.0f + expf(-x)); }

__device__ __forceinline__ void ldsm_x4(uint32_t* r, const void* p) {
    uint32_t addr = (uint32_t)__cvta_generic_to_shared(p);
    asm volatile("ldmatrix.sync.aligned.m8n8.x4.shared.b16 {%0,%1,%2,%3}, [%4];"
                 : "=r"(r[0]), "=r"(r[1]), "=r"(r[2]), "=r"(r[3]) : "r"(addr));
}
__device__ __forceinline__ void ldsm_x2(uint32_t* r, const void* p) {
    uint32_t addr = (uint32_t)__cvta_generic_to_shared(p);
    asm volatile("ldmatrix.sync.aligned.m8n8.x2.shared.b16 {%0,%1}, [%2];"
                 : "=r"(r[0]), "=r"(r[1]) : "r"(addr));
}
__device__ __forceinline__ void mma_bf16(float* c, const uint32_t* a, const uint32_t* b) {
    asm volatile(
        "mma.sync.aligned.m16n8k16.row.col.f32.bf16.bf16.f32 "
        "{%0,%1,%2,%3}, {%4,%5,%6,%7}, {%8,%9}, {%0,%1,%2,%3};"
        : "+f"(c[0]), "+f"(c[1]), "+f"(c[2]), "+f"(c[3])
        : "r"(a[0]), "r"(a[1]), "r"(a[2]), "r"(a[3]), "r"(b[0]), "r"(b[1]));
}
__device__ __forceinline__ void cp_async16(void* dst, const void* src, int sz) {
    uint32_t d = (uint32_t)__cvta_generic_to_shared(dst);
    asm volatile("cp.async.cg.shared.global [%0], [%1], 16, %2;"
                 :: "r"(d), "l"(src), "r"(sz));
}
__device__ __forceinline__ void cp_commit() { asm volatile("cp.async.commit_group;"); }
template <int N>
__device__ __forceinline__ void cp_wait() {
    asm volatile("cp.async.wait_group %0;" :: "n"(N));
}

// ---------------- prep_a: lin0 (+h into g_mh) + degi zero + boff ----------------
#define PA_LIN0 (Nn * Dd)
#define PA_TOT  (PA_LIN0 + Nn + Bb + 1)
__global__ void prep_a_kernel(const float* __restrict__ x,
                              const float* __restrict__ w,
                              const float* __restrict__ bvec,
                              const int* __restrict__ batch) {
    int idx = blockIdx.x * blockDim.x + threadIdx.x;
    if (idx < PA_LIN0) {
        int n = idx >> 6, o = idx & 63;
        float acc = bvec[o];
        const float* xr = x + n * 15;
        const float* wr = w + o * 15;
#pragma unroll
        for (int j = 0; j < 15; j++) acc = fmaf(xr[j], wr[j], acc);
        float h = fmaxf(acc, 0.0f);
        g_h[idx] = h;
        g_mh[n * 128 + 64 + o] = __float2bfloat16_rn(h);
    } else if (idx < PA_LIN0 + Nn) {
        g_degi[idx - PA_LIN0] = 0;
    } else if (idx < PA_TOT) {
        int b = idx - PA_LIN0 - Nn;
        int lo = 0, hi = Nn;
        while (lo < hi) {
            int mid = (lo + hi) >> 1;
            if (batch[mid] < b) lo = mid + 1; else hi = mid;
        }
        g_boff[b] = lo;
    }
}

// ---------------- prep_b: w2 conv + ehid + deg atomics + WcatT build ------------
#define PB_W2   (DDf * EHh)
#define PB_EH   (Ee * EHh)
#define PB_WC   (384 * 128)
#define PB_TOT  (PB_W2 + PB_EH + Ee + PB_WC)
__global__ void prep_b_kernel(const float* __restrict__ w2,
                              const float* __restrict__ ea,
                              const float* __restrict__ w1,
                              const float* __restrict__ b1,
                              const int* __restrict__ edge_index,
                              const float* __restrict__ wih,
                              const float* __restrict__ whh) {
    int idx = blockIdx.x * blockDim.x + threadIdx.x;
    if (idx < PB_W2) {
        g_W2b[idx] = __float2bfloat16_rn(w2[idx]);
    } else if (idx < PB_W2 + PB_EH) {
        int t = idx - PB_W2;
        int e = t >> 7, k = t & 127;
        float acc = b1[k];
        const float* er = ea + e * 5;
        const float* wr = w1 + k * 5;
#pragma unroll
        for (int j = 0; j < 5; j++) acc = fmaf(er[j], wr[j], acc);
        g_Hb[t] = __float2bfloat16_rn(fmaxf(acc, 0.0f));
    } else if (idx < PB_W2 + PB_EH + Ee) {
        int e = idx - PB_W2 - PB_EH;
        atomicAdd(&g_degi[edge_index[Ee + e]], 1);
    } else if (idx < PB_TOT) {
        int q = idx - PB_W2 - PB_EH - Ee;
        int j = q >> 7, k = q & 127;      // output gate j (0..383), input k (0..127)
        float v = 0.0f;
        if (k < 64) { if (j < 192) v = wih[j * 64 + k]; }
        else        { if (j >= 192) v = whh[(j - 192) * 64 + (k - 64)]; }
        g_WcatT[j * 128 + k] = __float2bfloat16_rn(v);
    }
}

// ---------------- csr: single-block scan + invdeg + fill ------------------------
__global__ void csr_kernel(const int* __restrict__ edge_index) {
    extern __shared__ int scur[];           // [Nn] dyn smem (60000 B)
    __shared__ int part[1024];
    const int t = threadIdx.x;
    int loc[15];
    int s = 0;
#pragma unroll
    for (int j = 0; j < 15; j++) {
        int idx = t * 15 + j;
        int v = (idx < Nn) ? g_degi[idx] : 0;
        loc[j] = s; s += v;
    }
    part[t] = s;
    __syncthreads();
    for (int off = 1; off < 1024; off <<= 1) {
        int v = (t >= off) ? part[t - off] : 0;
        __syncthreads();
        part[t] += v;
        __syncthreads();
    }
    int excl = part[t] - s;
#pragma unroll
    for (int j = 0; j < 15; j++) {
        int idx = t * 15 + j;
        if (idx < Nn) {
            g_eoff[idx] = excl + loc[j];
            g_invdeg[idx] = 1.0f / fmaxf((float)g_degi[idx], 1.0f);
        }
    }
    if (t == 0) g_eoff[Nn] = Ee;
    for (int i = t; i < Nn; i += 1024) scur[i] = 0;
    __syncthreads();
    for (int e = t; e < Ee; e += 1024) {
        int tgt = edge_index[Ee + e];
        int pos = atomicAdd(&scur[tgt], 1);
        g_perm[g_eoff[tgt] + pos] = e;
    }
}

// ---------------- ew GEMM: single-shot full-K tiles (measured 240us) ------------
#define SPAD 136
__global__ void __launch_bounds__(256) gemm_ew_mma(const float* __restrict__ b2) {
    extern __shared__ __align__(16) __nv_bfloat16 smem[];
    __nv_bfloat16* As = smem;
    __nv_bfloat16* Bs = smem + 128 * SPAD;

    const int bm = blockIdx.y;
    const int bn = blockIdx.x;
    const int tid = threadIdx.x;
    const int warp = tid >> 5, lane = tid & 31;
    const int wm = (warp >> 2) * 64;
    const int wn = (warp & 3) * 32;

#pragma unroll
    for (int u = tid; u < 2048; u += 256) {
        int r = u >> 4, c = (u & 15) * 8;
        int grow = bm * 128 + r;
        cp_async16(&As[r * SPAD + c], &g_Hb[(size_t)grow * 128 + c],
                   (grow < Ee) ? 16 : 0);
        cp_async16(&Bs[r * SPAD + c], &g_W2b[(size_t)(bn * 128 + r) * 128 + c], 16);
    }
    cp_commit();
    cp_wait<0>();
    __syncthreads();

    float acc[4][4][4];
#pragma unroll
    for (int mi = 0; mi < 4; mi++)
#pragma unroll
        for (int ni = 0; ni < 4; ni++)
#pragma unroll
            for (int r = 0; r < 4; r++) acc[mi][ni][r] = 0.0f;

    const int lrow = lane & 15;
    const int lcol8 = ((lane >> 4) & 1) * 8;
    const int lbrow = lane & 7;
    const int lbcol8 = ((lane >> 3) & 1) * 8;

#pragma unroll
    for (int k0 = 0; k0 < 128; k0 += 16) {
        uint32_t a[4][4], b[4][2];
#pragma unroll
        for (int mi = 0; mi < 4; mi++)
            ldsm_x4(a[mi], &As[(wm + mi * 16 + lrow) * SPAD + k0 + lcol8]);
#pragma unroll
        for (int ni = 0; ni < 4; ni++)
            ldsm_x2(b[ni], &Bs[(wn + ni * 8 + lbrow) * SPAD + k0 + lbcol8]);
#pragma unroll
        for (int mi = 0; mi < 4; mi++)
#pragma unroll
            for (int ni = 0; ni < 4; ni++)
                mma_bf16(acc[mi][ni], a[mi], b[ni]);
    }
    __syncthreads();

    __nv_bfloat16* stage = As;
    const int r0 = lane >> 2;
    const int c0 = (lane & 3) * 2;
#pragma unroll
    for (int mi = 0; mi < 4; mi++) {
#pragma unroll
        for (int ni = 0; ni < 4; ni++) {
            int cl = wn + ni * 8 + c0;
            float bb0 = b2[bn * 128 + cl], bb1 = b2[bn * 128 + cl + 1];
            int rl = wm + mi * 16 + r0;
            __nv_bfloat162 v;
            v.x = __float2bfloat16_rn(acc[mi][ni][0] + bb0);
            v.y = __float2bfloat16_rn(acc[mi][ni][1] + bb1);
            *(__nv_bfloat162*)&stage[rl * SPAD + cl] = v;
            v.x = __float2bfloat16_rn(acc[mi][ni][2] + bb0);
            v.y = __float2bfloat16_rn(acc[mi][ni][3] + bb1);
            *(__nv_bfloat162*)&stage[(rl + 8) * SPAD + cl] = v;
        }
    }
    __syncthreads();
#pragma unroll
    for (int p = 0; p < 8; p++) {
        int idx = tid + p * 256;
        int row = idx >> 4, c8 = (idx & 15) * 8;
        int grow = bm * 128 + row;
        if (grow < Ee)
            *(uint4*)&g_ewb[(size_t)grow * DDf + bn * 128 + c8] =
                *(const uint4*)&stage[row * SPAD + c8];
    }
}

// ---------------- msgagg: warp-per-node CSR, uint4 streaming, writes m bf16 -----
__global__ void __launch_bounds__(256) msgagg_kernel(const int* __restrict__ edge_index,
                                                     const float* __restrict__ conv_b) {
    const int warp = threadIdx.x >> 5, lane = threadIdx.x & 31;
    const int n = blockIdx.x * 8 + warp;
    __shared__ float xs[8][64];
    if (n >= Nn) return;
    const int j0 = g_eoff[n], j1 = g_eoff[n + 1];
    const int r = lane >> 3;            // 0..3
    const int c8 = (lane & 7) * 8;      // output group base
    float acc[8];
#pragma unroll
    for (int j = 0; j < 8; j++) acc[j] = 0.0f;

    for (int j = j0; j < j1; j++) {
        int e = g_perm[j];
        int s = edge_index[e];
        const float* xr = g_h + s * 64;
        xs[warp][lane] = xr[lane];
        xs[warp][lane + 32] = xr[lane + 32];
        __syncwarp();
        const __nv_bfloat16* wp = g_ewb + (size_t)e * DDf + c8;
#pragma unroll
        for (int t = 0; t < 16; t++) {
            int i = t * 4 + r;
            uint4 v = *(const uint4*)(wp + (size_t)i * 64);
            float xi = xs[warp][i];
            const __nv_bfloat162* p = (const __nv_bfloat162*)&v;
            acc[0] = fmaf(xi, __bfloat162float(p[0].x), acc[0]);
            acc[1] = fmaf(xi, __bfloat162float(p[0].y), acc[1]);
            acc[2] = fmaf(xi, __bfloat162float(p[1].x), acc[2]);
            acc[3] = fmaf(xi, __bfloat162float(p[1].y), acc[3]);
            acc[4] = fmaf(xi, __bfloat162float(p[2].x), acc[4]);
            acc[5] = fmaf(xi, __bfloat162float(p[2].y), acc[5]);
            acc[6] = fmaf(xi, __bfloat162float(p[3].x), acc[6]);
            acc[7] = fmaf(xi, __bfloat162float(p[3].y), acc[7]);
        }
        __syncwarp();
    }
    const unsigned FULL = 0xffffffffu;
#pragma unroll
    for (int j = 0; j < 8; j++) {
        acc[j] += __shfl_xor_sync(FULL, acc[j], 8);
        acc[j] += __shfl_xor_sync(FULL, acc[j], 16);
    }
    if (lane < 8) {
        float inv = g_invdeg[n];
        __nv_bfloat16 mv[8];
#pragma unroll
        for (int j = 0; j < 8; j++) {
            float m = fmaxf(fmaf(acc[j], inv, conv_b[lane * 8 + j]), 0.0f);
            mv[j] = __float2bfloat16_rn(m);
        }
        *(uint4*)&g_mh[n * 128 + lane * 8] = *(const uint4*)mv;
    }
}

// ---------------- gates GEMM: g_gates[N,384] = g_mh[N,128] @ g_WcatT^T ----------
__global__ void __launch_bounds__(256) gemm_gates_mma() {
    extern __shared__ __align__(16) __nv_bfloat16 smem[];
    __nv_bfloat16* As = smem;                 // [128][136]
    __nv_bfloat16* Bs = smem + 128 * SPAD;    // [128][136]

    const int bm = blockIdx.y;   // 0..117
    const int bn = blockIdx.x;   // 0..2
    const int tid = threadIdx.x;
    const int warp = tid >> 5, lane = tid & 31;
    const int wm = (warp >> 2) * 64;
    const int wn = (warp & 3) * 32;

#pragma unroll
    for (int u = tid; u < 2048; u += 256) {
        int r = u >> 4, c = (u & 15) * 8;
        int grow = bm * 128 + r;
        cp_async16(&As[r * SPAD + c], &g_mh[(size_t)grow * 128 + c],
                   (grow < Nn) ? 16 : 0);
        cp_async16(&Bs[r * SPAD + c], &g_WcatT[(bn * 128 + r) * 128 + c], 16);
    }
    cp_commit();
    cp_wait<0>();
    __syncthreads();

    float acc[4][4][4];
#pragma unroll
    for (int mi = 0; mi < 4; mi++)
#pragma unroll
        for (int ni = 0; ni < 4; ni++)
#pragma unroll
            for (int r = 0; r < 4; r++) acc[mi][ni][r] = 0.0f;

    const int lrow = lane & 15;
    const int lcol8 = ((lane >> 4) & 1) * 8;
    const int lbrow = lane & 7;
    const int lbcol8 = ((lane >> 3) & 1) * 8;

#pragma unroll
    for (int k0 = 0; k0 < 128; k0 += 16) {
        uint32_t a[4][4], b[4][2];
#pragma unroll
        for (int mi = 0; mi < 4; mi++)
            ldsm_x4(a[mi], &As[(wm + mi * 16 + lrow) * SPAD + k0 + lcol8]);
#pragma unroll
        for (int ni = 0; ni < 4; ni++)
            ldsm_x2(b[ni], &Bs[(wn + ni * 8 + lbrow) * SPAD + k0 + lbcol8]);
#pragma unroll
        for (int mi = 0; mi < 4; mi++)
#pragma unroll
            for (int ni = 0; ni < 4; ni++)
                mma_bf16(acc[mi][ni], a[mi], b[ni]);
    }

    const int r0 = lane >> 2;
    const int c0 = (lane & 3) * 2;
#pragma unroll
    for (int mi = 0; mi < 4; mi++) {
#pragma unroll
        for (int ni = 0; ni < 4; ni++) {
            int gc = bn * 128 + wn + ni * 8 + c0;
            int grow = bm * 128 + wm + mi * 16 + r0;
            if (grow < Nn)
                *(float2*)&g_gates[(size_t)grow * 384 + gc] =
                    make_float2(acc[mi][ni][0], acc[mi][ni][1]);
            if (grow + 8 < Nn)
                *(float2*)&g_gates[(size_t)(grow + 8) * 384 + gc] =
                    make_float2(acc[mi][ni][2], acc[mi][ni][3]);
        }
    }
}

// ---------------- GRU gate epilogue (elementwise) --------------------------------
__global__ void gru_epi_kernel(const float* __restrict__ b_ih,
                               const float* __restrict__ b_hh) {
    int idx = blockIdx.x * blockDim.x + threadIdx.x;
    if (idx >= Nn * 64) return;
    int n = idx >> 6, d = idx & 63;
    const float* gr = g_gates + (size_t)n * 384;
    float gi_r = gr[d]       + b_ih[d];
    float gi_z = gr[64 + d]  + b_ih[64 + d];
    float gi_n = gr[128 + d] + b_ih[128 + d];
    float gh_r = gr[192 + d]       + b_hh[d];
    float gh_z = gr[192 + 64 + d]  + b_hh[64 + d];
    float gh_n = gr[192 + 128 + d] + b_hh[128 + d];
    float rg = sigm(gi_r + gh_r);
    float zg = sigm(gi_z + gh_z);
    float ng = tanhf(fmaf(rg, gh_n, gi_n));
    float hv = g_h[idx];
    float h = (1.0f - zg) * ng + zg * hv;
    g_h[idx] = h;
    g_mh[n * 128 + 64 + d] = __float2bfloat16_rn(h);
}

// ---------------- fused Set2Set (6 steps) + output MLP, one block per graph -----
__global__ void __launch_bounds__(256) set2set_kernel(
    const float* __restrict__ w_ih, const float* __restrict__ w_hh,
    const float* __restrict__ b_ih, const float* __restrict__ b_hh,
    const float* __restrict__ lin1_w, const float* __restrict__ lin1_b,
    const float* __restrict__ lin2_w, const float* __restrict__ lin2_b,
    float* __restrict__ out) {
    const int b = blockIdx.x;
    const int tid = threadIdx.x;
    const int lane = tid & 31, w = tid >> 5;
    __shared__ float q[128], hl[64], cl[64], g[256];
    __shared__ float red[8];
    __shared__ float rpart[8][64];
    __shared__ float emax_s, denom_s;
    __shared__ float z[64];

    if (tid < 128) q[tid] = 0.0f;
    if (tid < 64) { hl[tid] = 0.0f; cl[tid] = 0.0f; }
    __syncthreads();

    const int s = g_boff[b], epos = g_boff[b + 1];
    const unsigned FULL = 0xffffffffu;

    for (int step = 0; step < NSTEPS; step++) {
        {
            int j = tid;
            float acc = b_ih[j] + b_hh[j];
            const float* wr = w_ih + j * 128;
#pragma unroll 8
            for (int k = 0; k < 128; k++) acc = fmaf(q[k], wr[k], acc);
            const float* wr2 = w_hh + j * 64;
#pragma unroll 8
            for (int k = 0; k < 64; k++) acc = fmaf(hl[k], wr2[k], acc);
            g[j] = acc;
        }
        __syncthreads();
        if (tid < 64) {
            int d = tid;
            float ig = g[d], fg = g[64 + d], gg = g[128 + d], og = g[192 + d];
            float c = sigm(fg) * cl[d] + sigm(ig) * tanhf(gg);
            cl[d] = c;
            hl[d] = sigm(og) * tanhf(c);
        }
        __syncthreads();

        float lmax = -FLT_MAX;
        for (int n = s + w; n < epos; n += 8) {
            const float* hr = g_h + n * 64;
            float v = hr[lane] * hl[lane] + hr[32 + lane] * hl[32 + lane];
#pragma unroll
            for (int off = 16; off > 0; off >>= 1) v += __shfl_down_sync(FULL, v, off);
            v = __shfl_sync(FULL, v, 0);
            lmax = fmaxf(lmax, v);
        }
        if (lane == 0) red[w] = lmax;
        __syncthreads();
        if (tid == 0) {
            float m = red[0];
#pragma unroll
            for (int i = 1; i < 8; i++) m = fmaxf(m, red[i]);
            emax_s = m;
        }
        __syncthreads();
        float emax = emax_s;

        float lsum = 0.0f, r0 = 0.0f, r1 = 0.0f;
        for (int n = s + w; n < epos; n += 8) {
            const float* hr = g_h + n * 64;
            float x0 = hr[lane], x1 = hr[32 + lane];
            float v = x0 * hl[lane] + x1 * hl[32 + lane];
#pragma unroll
            for (int off = 16; off > 0; off >>= 1) v += __shfl_down_sync(FULL, v, off);
            v = __shfl_sync(FULL, v, 0);
            float ex = expf(v - emax);
            lsum += ex;
            r0 = fmaf(ex, x0, r0);
            r1 = fmaf(ex, x1, r1);
        }
        if (lane == 0) red[w] = lsum;
        rpart[w][lane] = r0;
        rpart[w][32 + lane] = r1;
        __syncthreads();
        if (tid == 0) {
            float ssum = 0.0f;
#pragma unroll
            for (int i = 0; i < 8; i++) ssum += red[i];
            denom_s = ssum;
        }
        __syncthreads();
        if (tid < 64) {
            float rv = 0.0f;
#pragma unroll
            for (int i = 0; i < 8; i++) rv += rpart[i][tid];
            q[64 + tid] = rv / (denom_s + 1e-16f);
            q[tid] = hl[tid];
        }
        __syncthreads();
    }

    if (tid < 64) {
        float acc = lin1_b[tid];
        const float* wr = lin1_w + tid * 128;
#pragma unroll 8
        for (int k = 0; k < 128; k++) acc = fmaf(q[k], wr[k], acc);
        z[tid] = fmaxf(acc, 0.0f);
    }
    __syncthreads();
    if (tid < 12) {
        float acc = lin2_b[tid];
        const float* wr = lin2_w + tid * 64;
#pragma unroll
        for (int d = 0; d < 64; d++) acc = fmaf(z[d], wr[d], acc);
        out[b * 12 + tid] = acc;
    }
}

// ---------------- launch ----------------
extern "C" void kernel_launch(void* const* d_in, const int* in_sizes, int n_in,
                              void* d_out, int out_size) {
    const float* x         = (const float*)d_in[0];
    const float* edge_attr = (const float*)d_in[1];
    const int*   edge_index= (const int*)  d_in[2];
    const int*   batch     = (const int*)  d_in[3];
    const float* lin0_w    = (const float*)d_in[4];
    const float* lin0_b    = (const float*)d_in[5];
    const float* en_w1     = (const float*)d_in[6];
    const float* en_b1     = (const float*)d_in[7];
    const float* en_w2     = (const float*)d_in[8];
    const float* en_b2     = (const float*)d_in[9];
    const float* conv_b    = (const float*)d_in[10];
    const float* gru_w_ih  = (const float*)d_in[11];
    const float* gru_w_hh  = (const float*)d_in[12];
    const float* gru_b_ih  = (const float*)d_in[13];
    const float* gru_b_hh  = (const float*)d_in[14];
    const float* lstm_w_ih = (const float*)d_in[15];
    const float* lstm_w_hh = (const float*)d_in[16];
    const float* lstm_b_ih = (const float*)d_in[17];
    const float* lstm_b_hh = (const float*)d_in[18];
    const float* lin1_w    = (const float*)d_in[19];
    const float* lin1_b    = (const float*)d_in[20];
    const float* lin2_w    = (const float*)d_in[21];
    const float* lin2_b    = (const float*)d_in[22];
    float* out = (float*)d_out;

    const int gemm_smem = 2 * 128 * SPAD * (int)sizeof(__nv_bfloat16);  // 69632
    cudaFuncSetAttribute(gemm_ew_mma, cudaFuncAttributeMaxDynamicSharedMemorySize,
                         gemm_smem);
    cudaFuncSetAttribute(gemm_gates_mma, cudaFuncAttributeMaxDynamicSharedMemorySize,
                         gemm_smem);
    cudaFuncSetAttribute(csr_kernel, cudaFuncAttributeMaxDynamicSharedMemorySize,
                         Nn * (int)sizeof(int));

    // 1: prep_a (lin0 + degi zero + boff)
    prep_a_kernel<<<(PA_TOT + 255) / 256, 256>>>(x, lin0_w, lin0_b, batch);
    // 2: prep_b (w2->bf16 + ehid + deg + WcatT)
    prep_b_kernel<<<(PB_TOT + 255) / 256, 256>>>(en_w2, edge_attr, en_w1, en_b1,
                                                 edge_index, gru_w_ih, gru_w_hh);
    // 3: CSR (scan + invdeg + fill) in one block
    csr_kernel<<<1, 1024, Nn * sizeof(int)>>>(edge_index);
    // 4: ew GEMM (profiled slot)
    dim3 gemm_grid(DDf / 128, (Ee + 127) / 128);
    gemm_ew_mma<<<gemm_grid, 256, gemm_smem>>>(en_b2);

    dim3 gates_grid(3, (Nn + 127) / 128);
    for (int s = 0; s < NSTEPS; s++) {
        msgagg_kernel<<<(Nn + 7) / 8, 256>>>(edge_index, conv_b);
        gemm_gates_mma<<<gates_grid, 256, gemm_smem>>>();
        gru_epi_kernel<<<(Nn * 64 + 255) / 256, 256>>>(gru_b_ih, gru_b_hh);
    }

    set2set_kernel<<<Bb, 256>>>(lstm_w_ih, lstm_w_hh, lstm_b_ih, lstm_b_hh,
                                lin1_w, lin1_b, lin2_w, lin2_b, out);
}

// round 7
// speedup vs baseline: 1.2729x; 1.0052x over previous
#include <cuda_runtime.h>
#include <cuda_bf16.h>
#include <math.h>
#include <float.h>
#include <stdint.h>

#define Nn 15000
#define Ee 60000
#define Bb 512
#define Dd 64
#define EHh 128
#define DDf 4096   // D*D
#define NSTEPS 6

// ---------------- device scratch ----------------
static __device__ __nv_bfloat16 g_Hb[(size_t)Ee * EHh];    // edge hidden, CSR order
static __device__ __nv_bfloat16 g_W2b[(size_t)DDf * EHh];  // en_w2 bf16 [4096,128]
static __device__ __nv_bfloat16 g_ewb[(size_t)Ee * DDf];   // edge weights, CSR order
static __device__ __nv_bfloat16 g_xg[(size_t)Ee * 64];     // gathered src features, CSR
static __device__ float g_h[Nn * Dd];                      // node state fp32 (master)
static __device__ __nv_bfloat16 g_mh[Nn * 128];            // [m | h] per node, bf16
static __device__ float g_gates[(size_t)Nn * 384];         // gates GEMM out
static __device__ __nv_bfloat16 g_WcatT[384 * 128];        // block-diag GRU weights^T
static __device__ float g_invdeg[Nn];
static __device__ int   g_degi[Nn];
static __device__ int   g_eoff[Nn + 1];                    // CSR offsets by target
static __device__ int   g_perm[Ee];                        // edge ids grouped by target
static __device__ int   g_src[Ee];                         // src node per CSR pos
static __device__ int   g_boff[Bb + 1];                    // batch segment offsets

// ---------------- small helpers ----------------
__device__ __forceinline__ float sigm(float x) { return 1.0f / (1.0f + expf(-x)); }

__device__ __forceinline__ void ldsm_x4(uint32_t* r, const void* p) {
    uint32_t addr = (uint32_t)__cvta_generic_to_shared(p);
    asm volatile("ldmatrix.sync.aligned.m8n8.x4.shared.b16 {%0,%1,%2,%3}, [%4];"
                 : "=r"(r[0]), "=r"(r[1]), "=r"(r[2]), "=r"(r[3]) : "r"(addr));
}
__device__ __forceinline__ void ldsm_x2(uint32_t* r, const void* p) {
    uint32_t addr = (uint32_t)__cvta_generic_to_shared(p);
    asm volatile("ldmatrix.sync.aligned.m8n8.x2.shared.b16 {%0,%1}, [%2];"
                 : "=r"(r[0]), "=r"(r[1]) : "r"(addr));
}
__device__ __forceinline__ void mma_bf16(float* c, const uint32_t* a, const uint32_t* b) {
    asm volatile(
        "mma.sync.aligned.m16n8k16.row.col.f32.bf16.bf16.f32 "
        "{%0,%1,%2,%3}, {%4,%5,%6,%7}, {%8,%9}, {%0,%1,%2,%3};"
        : "+f"(c[0]), "+f"(c[1]), "+f"(c[2]), "+f"(c[3])
        : "r"(a[0]), "r"(a[1]), "r"(a[2]), "r"(a[3]), "r"(b[0]), "r"(b[1]));
}
__device__ __forceinline__ void cp_async16(void* dst, const void* src, int sz) {
    uint32_t d = (uint32_t)__cvta_generic_to_shared(dst);
    asm volatile("cp.async.cg.shared.global [%0], [%1], 16, %2;"
                 :: "r"(d), "l"(src), "r"(sz));
}
__device__ __forceinline__ void cp_commit() { asm volatile("cp.async.commit_group;"); }
template <int N>
__device__ __forceinline__ void cp_wait() {
    asm volatile("cp.async.wait_group %0;" :: "n"(N));
}

// ---------------- prep_a: lin0 (+h into g_mh) + degi zero + boff ----------------
#define PA_LIN0 (Nn * Dd)
#define PA_TOT  (PA_LIN0 + Nn + Bb + 1)
__global__ void prep_a_kernel(const float* __restrict__ x,
                              const float* __restrict__ w,
                              const float* __restrict__ bvec,
                              const int* __restrict__ batch) {
    int idx = blockIdx.x * blockDim.x + threadIdx.x;
    if (idx < PA_LIN0) {
        int n = idx >> 6, o = idx & 63;
        float acc = bvec[o];
        const float* xr = x + n * 15;
        const float* wr = w + o * 15;
#pragma unroll
        for (int j = 0; j < 15; j++) acc = fmaf(xr[j], wr[j], acc);
        float h = fmaxf(acc, 0.0f);
        g_h[idx] = h;
        g_mh[n * 128 + 64 + o] = __float2bfloat16_rn(h);
    } else if (idx < PA_LIN0 + Nn) {
        g_degi[idx - PA_LIN0] = 0;
    } else if (idx < PA_TOT) {
        int b = idx - PA_LIN0 - Nn;
        int lo = 0, hi = Nn;
        while (lo < hi) {
            int mid = (lo + hi) >> 1;
            if (batch[mid] < b) lo = mid + 1; else hi = mid;
        }
        g_boff[b] = lo;
    }
}

// ---------------- prep_b1: w2 conv + deg atomics + WcatT build -------------------
#define PB1_W2  (DDf * EHh)
#define PB1_WC  (384 * 128)
#define PB1_TOT (PB1_W2 + Ee + PB1_WC)
__global__ void prep_b1_kernel(const float* __restrict__ w2,
                               const int* __restrict__ edge_index,
                               const float* __restrict__ wih,
                               const float* __restrict__ whh) {
    int idx = blockIdx.x * blockDim.x + threadIdx.x;
    if (idx < PB1_W2) {
        g_W2b[idx] = __float2bfloat16_rn(w2[idx]);
    } else if (idx < PB1_W2 + Ee) {
        int e = idx - PB1_W2;
        atomicAdd(&g_degi[edge_index[Ee + e]], 1);
    } else if (idx < PB1_TOT) {
        int q = idx - PB1_W2 - Ee;
        int j = q >> 7, k = q & 127;
        float v = 0.0f;
        if (k < 64) { if (j < 192) v = wih[j * 64 + k]; }
        else        { if (j >= 192) v = whh[(j - 192) * 64 + (k - 64)]; }
        g_WcatT[j * 128 + k] = __float2bfloat16_rn(v);
    }
}

// ---------------- csr: single-block scan + invdeg + fill ------------------------
__global__ void csr_kernel(const int* __restrict__ edge_index) {
    extern __shared__ int scur[];           // [Nn]
    __shared__ int part[1024];
    const int t = threadIdx.x;
    int loc[15];
    int s = 0;
#pragma unroll
    for (int j = 0; j < 15; j++) {
        int idx = t * 15 + j;
        int v = (idx < Nn) ? g_degi[idx] : 0;
        loc[j] = s; s += v;
    }
    part[t] = s;
    __syncthreads();
    for (int off = 1; off < 1024; off <<= 1) {
        int v = (t >= off) ? part[t - off] : 0;
        __syncthreads();
        part[t] += v;
        __syncthreads();
    }
    int excl = part[t] - s;
#pragma unroll
    for (int j = 0; j < 15; j++) {
        int idx = t * 15 + j;
        if (idx < Nn) {
            g_eoff[idx] = excl + loc[j];
            g_invdeg[idx] = 1.0f / fmaxf((float)g_degi[idx], 1.0f);
        }
    }
    if (t == 0) g_eoff[Nn] = Ee;
    for (int i = t; i < Nn; i += 1024) scur[i] = 0;
    __syncthreads();
    for (int e = t; e < Ee; e += 1024) {
        int tgt = edge_index[Ee + e];
        int pos = atomicAdd(&scur[tgt], 1);
        g_perm[g_eoff[tgt] + pos] = e;
    }
}

// ---------------- prep_b2: ehid in CSR order + src array -------------------------
#define PB2_EH (Ee * EHh)
#define PB2_TOT (PB2_EH + Ee)
__global__ void prep_b2_kernel(const float* __restrict__ ea,
                               const float* __restrict__ w1,
                               const float* __restrict__ b1,
                               const int* __restrict__ edge_index) {
    int idx = blockIdx.x * blockDim.x + threadIdx.x;
    if (idx < PB2_EH) {
        int pos = idx >> 7, k = idx & 127;
        int e = g_perm[pos];
        float acc = b1[k];
        const float* er = ea + e * 5;
        const float* wr = w1 + k * 5;
#pragma unroll
        for (int j = 0; j < 5; j++) acc = fmaf(er[j], wr[j], acc);
        g_Hb[idx] = __float2bfloat16_rn(fmaxf(acc, 0.0f));
    } else if (idx < PB2_TOT) {
        int pos = idx - PB2_EH;
        g_src[pos] = edge_index[g_perm[pos]];
    }
}

// ---------------- ew GEMM: single-shot full-K tiles (measured 240us) ------------
#define SPAD 136
__global__ void __launch_bounds__(256) gemm_ew_mma(const float* __restrict__ b2) {
    extern __shared__ __align__(16) __nv_bfloat16 smem[];
    __nv_bfloat16* As = smem;
    __nv_bfloat16* Bs = smem + 128 * SPAD;

    const int bm = blockIdx.y;
    const int bn = blockIdx.x;
    const int tid = threadIdx.x;
    const int warp = tid >> 5, lane = tid & 31;
    const int wm = (warp >> 2) * 64;
    const int wn = (warp & 3) * 32;

#pragma unroll
    for (int u = tid; u < 2048; u += 256) {
        int r = u >> 4, c = (u & 15) * 8;
        int grow = bm * 128 + r;
        cp_async16(&As[r * SPAD + c], &g_Hb[(size_t)grow * 128 + c],
                   (grow < Ee) ? 16 : 0);
        cp_async16(&Bs[r * SPAD + c], &g_W2b[(size_t)(bn * 128 + r) * 128 + c], 16);
    }
    cp_commit();
    cp_wait<0>();
    __syncthreads();

    float acc[4][4][4];
#pragma unroll
    for (int mi = 0; mi < 4; mi++)
#pragma unroll
        for (int ni = 0; ni < 4; ni++)
#pragma unroll
            for (int r = 0; r < 4; r++) acc[mi][ni][r] = 0.0f;

    const int lrow = lane & 15;
    const int lcol8 = ((lane >> 4) & 1) * 8;
    const int lbrow = lane & 7;
    const int lbcol8 = ((lane >> 3) & 1) * 8;

#pragma unroll
    for (int k0 = 0; k0 < 128; k0 += 16) {
        uint32_t a[4][4], b[4][2];
#pragma unroll
        for (int mi = 0; mi < 4; mi++)
            ldsm_x4(a[mi], &As[(wm + mi * 16 + lrow) * SPAD + k0 + lcol8]);
#pragma unroll
        for (int ni = 0; ni < 4; ni++)
            ldsm_x2(b[ni], &Bs[(wn + ni * 8 + lbrow) * SPAD + k0 + lbcol8]);
#pragma unroll
        for (int mi = 0; mi < 4; mi++)
#pragma unroll
            for (int ni = 0; ni < 4; ni++)
                mma_bf16(acc[mi][ni], a[mi], b[ni]);
    }
    __syncthreads();

    __nv_bfloat16* stage = As;
    const int r0 = lane >> 2;
    const int c0 = (lane & 3) * 2;
#pragma unroll
    for (int mi = 0; mi < 4; mi++) {
#pragma unroll
        for (int ni = 0; ni < 4; ni++) {
            int cl = wn + ni * 8 + c0;
            float bb0 = b2[bn * 128 + cl], bb1 = b2[bn * 128 + cl + 1];
            int rl = wm + mi * 16 + r0;
            __nv_bfloat162 v;
            v.x = __float2bfloat16_rn(acc[mi][ni][0] + bb0);
            v.y = __float2bfloat16_rn(acc[mi][ni][1] + bb1);
            *(__nv_bfloat162*)&stage[rl * SPAD + cl] = v;
            v.x = __float2bfloat16_rn(acc[mi][ni][2] + bb0);
            v.y = __float2bfloat16_rn(acc[mi][ni][3] + bb1);
            *(__nv_bfloat162*)&stage[(rl + 8) * SPAD + cl] = v;
        }
    }
    __syncthreads();
#pragma unroll
    for (int p = 0; p < 8; p++) {
        int idx = tid + p * 256;
        int row = idx >> 4, c8 = (idx & 15) * 8;
        int grow = bm * 128 + row;
        if (grow < Ee)
            *(uint4*)&g_ewb[(size_t)grow * DDf + bn * 128 + c8] =
                *(const uint4*)&stage[row * SPAD + c8];
    }
}

// ---------------- per-step gather: xg[pos] = h_bf16[src[pos]] --------------------
__global__ void gather_x_kernel() {
    int idx = blockIdx.x * blockDim.x + threadIdx.x;
    if (idx >= Ee * 8) return;
    int pos = idx >> 3, q = idx & 7;
    int src = g_src[pos];
    uint4 v = *(const uint4*)&g_mh[src * 128 + 64 + q * 8];
    *(uint4*)&g_xg[(size_t)pos * 64 + q * 8] = v;
}

// ---------------- msgagg v3: pure linear stream, warp per node, no smem ----------
__global__ void __launch_bounds__(256) msgagg_kernel(const float* __restrict__ conv_b) {
    const int warp = threadIdx.x >> 5, lane = threadIdx.x & 31;
    const int n = blockIdx.x * 8 + warp;
    if (n >= Nn) return;
    const int j0 = g_eoff[n], j1 = g_eoff[n + 1];
    const int r = lane >> 3;            // 0..3 : i ≡ r (mod 4)
    const int c8 = (lane & 7) * 8;      // output col base
    const unsigned FULL = 0xffffffffu;
    const uint32_t* xg32 = (const uint32_t*)g_xg;
    float acc[8];
#pragma unroll
    for (int j = 0; j < 8; j++) acc[j] = 0.0f;

#pragma unroll 2
    for (int j = j0; j < j1; j++) {
        uint32_t xv = xg32[j * 32 + lane];                 // pairs (2*lane, 2*lane+1)
        const __nv_bfloat16* wp = g_ewb + (size_t)j * DDf + c8;
#pragma unroll
        for (int t = 0; t < 16; t++) {
            int i = t * 4 + r;
            uint4 v = *(const uint4*)(wp + (size_t)i * 64);
            uint32_t xp = __shfl_sync(FULL, xv, 2 * t + (r >> 1));
            __nv_bfloat162 xpair = *(__nv_bfloat162*)&xp;
            float xi = (r & 1) ? __bfloat162float(xpair.y) : __bfloat162float(xpair.x);
            const __nv_bfloat162* p = (const __nv_bfloat162*)&v;
            acc[0] = fmaf(xi, __bfloat162float(p[0].x), acc[0]);
            acc[1] = fmaf(xi, __bfloat162float(p[0].y), acc[1]);
            acc[2] = fmaf(xi, __bfloat162float(p[1].x), acc[2]);
            acc[3] = fmaf(xi, __bfloat162float(p[1].y), acc[3]);
            acc[4] = fmaf(xi, __bfloat162float(p[2].x), acc[4]);
            acc[5] = fmaf(xi, __bfloat162float(p[2].y), acc[5]);
            acc[6] = fmaf(xi, __bfloat162float(p[3].x), acc[6]);
            acc[7] = fmaf(xi, __bfloat162float(p[3].y), acc[7]);
        }
    }
#pragma unroll
    for (int j = 0; j < 8; j++) {
        acc[j] += __shfl_xor_sync(FULL, acc[j], 8);
        acc[j] += __shfl_xor_sync(FULL, acc[j], 16);
    }
    if (lane < 8) {
        float inv = g_invdeg[n];
        __nv_bfloat16 mv[8];
#pragma unroll
        for (int j = 0; j < 8; j++) {
            float m = fmaxf(fmaf(acc[j], inv, conv_b[lane * 8 + j]), 0.0f);
            mv[j] = __float2bfloat16_rn(m);
        }
        *(uint4*)&g_mh[n * 128 + lane * 8] = *(const uint4*)mv;
    }
}

// ---------------- gates GEMM: g_gates[N,384] = g_mh[N,128] @ g_WcatT^T ----------
__global__ void __launch_bounds__(256) gemm_gates_mma() {
    extern __shared__ __align__(16) __nv_bfloat16 smem[];
    __nv_bfloat16* As = smem;
    __nv_bfloat16* Bs = smem + 128 * SPAD;

    const int bm = blockIdx.y;
    const int bn = blockIdx.x;
    const int tid = threadIdx.x;
    const int warp = tid >> 5, lane = tid & 31;
    const int wm = (warp >> 2) * 64;
    const int wn = (warp & 3) * 32;

#pragma unroll
    for (int u = tid; u < 2048; u += 256) {
        int r = u >> 4, c = (u & 15) * 8;
        int grow = bm * 128 + r;
        cp_async16(&As[r * SPAD + c], &g_mh[(size_t)grow * 128 + c],
                   (grow < Nn) ? 16 : 0);
        cp_async16(&Bs[r * SPAD + c], &g_WcatT[(bn * 128 + r) * 128 + c], 16);
    }
    cp_commit();
    cp_wait<0>();
    __syncthreads();

    float acc[4][4][4];
#pragma unroll
    for (int mi = 0; mi < 4; mi++)
#pragma unroll
        for (int ni = 0; ni < 4; ni++)
#pragma unroll
            for (int r = 0; r < 4; r++) acc[mi][ni][r] = 0.0f;

    const int lrow = lane & 15;
    const int lcol8 = ((lane >> 4) & 1) * 8;
    const int lbrow = lane & 7;
    const int lbcol8 = ((lane >> 3) & 1) * 8;

#pragma unroll
    for (int k0 = 0; k0 < 128; k0 += 16) {
        uint32_t a[4][4], b[4][2];
#pragma unroll
        for (int mi = 0; mi < 4; mi++)
            ldsm_x4(a[mi], &As[(wm + mi * 16 + lrow) * SPAD + k0 + lcol8]);
#pragma unroll
        for (int ni = 0; ni < 4; ni++)
            ldsm_x2(b[ni], &Bs[(wn + ni * 8 + lbrow) * SPAD + k0 + lbcol8]);
#pragma unroll
        for (int mi = 0; mi < 4; mi++)
#pragma unroll
            for (int ni = 0; ni < 4; ni++)
                mma_bf16(acc[mi][ni], a[mi], b[ni]);
    }

    const int r0 = lane >> 2;
    const int c0 = (lane & 3) * 2;
#pragma unroll
    for (int mi = 0; mi < 4; mi++) {
#pragma unroll
        for (int ni = 0; ni < 4; ni++) {
            int gc = bn * 128 + wn + ni * 8 + c0;
            int grow = bm * 128 + wm + mi * 16 + r0;
            if (grow < Nn)
                *(float2*)&g_gates[(size_t)grow * 384 + gc] =
                    make_float2(acc[mi][ni][0], acc[mi][ni][1]);
            if (grow + 8 < Nn)
                *(float2*)&g_gates[(size_t)(grow + 8) * 384 + gc] =
                    make_float2(acc[mi][ni][2], acc[mi][ni][3]);
        }
    }
}

// ---------------- GRU gate epilogue (elementwise) --------------------------------
__global__ void gru_epi_kernel(const float* __restrict__ b_ih,
                               const float* __restrict__ b_hh) {
    int idx = blockIdx.x * blockDim.x + threadIdx.x;
    if (idx >= Nn * 64) return;
    int n = idx >> 6, d = idx & 63;
    const float* gr = g_gates + (size_t)n * 384;
    float gi_r = gr[d]       + b_ih[d];
    float gi_z = gr[64 + d]  + b_ih[64 + d];
    float gi_n = gr[128 + d] + b_ih[128 + d];
    float gh_r = gr[192 + d]       + b_hh[d];
    float gh_z = gr[192 + 64 + d]  + b_hh[64 + d];
    float gh_n = gr[192 + 128 + d] + b_hh[128 + d];
    float rg = sigm(gi_r + gh_r);
    float zg = sigm(gi_z + gh_z);
    float ng = tanhf(fmaf(rg, gh_n, gi_n));
    float hv = g_h[idx];
    float h = (1.0f - zg) * ng + zg * hv;
    g_h[idx] = h;
    g_mh[n * 128 + 64 + d] = __float2bfloat16_rn(h);
}

// ---------------- fused Set2Set (6 steps) + output MLP ---------------------------
__global__ void __launch_bounds__(256) set2set_kernel(
    const float* __restrict__ w_ih, const float* __restrict__ w_hh,
    const float* __restrict__ b_ih, const float* __restrict__ b_hh,
    const float* __restrict__ lin1_w, const float* __restrict__ lin1_b,
    const float* __restrict__ lin2_w, const float* __restrict__ lin2_b,
    float* __restrict__ out) {
    const int b = blockIdx.x;
    const int tid = threadIdx.x;
    const int lane = tid & 31, w = tid >> 5;
    __shared__ float q[128], hl[64], cl[64], g[256];
    __shared__ float red[8];
    __shared__ float rpart[8][64];
    __shared__ float emax_s, denom_s;
    __shared__ float z[64];

    if (tid < 128) q[tid] = 0.0f;
    if (tid < 64) { hl[tid] = 0.0f; cl[tid] = 0.0f; }
    __syncthreads();

    const int s = g_boff[b], epos = g_boff[b + 1];
    const unsigned FULL = 0xffffffffu;

    for (int step = 0; step < NSTEPS; step++) {
        {
            int j = tid;
            float acc = b_ih[j] + b_hh[j];
            const float* wr = w_ih + j * 128;
#pragma unroll 8
            for (int k = 0; k < 128; k++) acc = fmaf(q[k], wr[k], acc);
            const float* wr2 = w_hh + j * 64;
#pragma unroll 8
            for (int k = 0; k < 64; k++) acc = fmaf(hl[k], wr2[k], acc);
            g[j] = acc;
        }
        __syncthreads();
        if (tid < 64) {
            int d = tid;
            float ig = g[d], fg = g[64 + d], gg = g[128 + d], og = g[192 + d];
            float c = sigm(fg) * cl[d] + sigm(ig) * tanhf(gg);
            cl[d] = c;
            hl[d] = sigm(og) * tanhf(c);
        }
        __syncthreads();

        float lmax = -FLT_MAX;
        for (int n = s + w; n < epos; n += 8) {
            const float* hr = g_h + n * 64;
            float v = hr[lane] * hl[lane] + hr[32 + lane] * hl[32 + lane];
#pragma unroll
            for (int off = 16; off > 0; off >>= 1) v += __shfl_down_sync(FULL, v, off);
            v = __shfl_sync(FULL, v, 0);
            lmax = fmaxf(lmax, v);
        }
        if (lane == 0) red[w] = lmax;
        __syncthreads();
        if (tid == 0) {
            float m = red[0];
#pragma unroll
            for (int i = 1; i < 8; i++) m = fmaxf(m, red[i]);
            emax_s = m;
        }
        __syncthreads();
        float emax = emax_s;

        float lsum = 0.0f, r0 = 0.0f, r1 = 0.0f;
        for (int n = s + w; n < epos; n += 8) {
            const float* hr = g_h + n * 64;
            float x0 = hr[lane], x1 = hr[32 + lane];
            float v = x0 * hl[lane] + x1 * hl[32 + lane];
#pragma unroll
            for (int off = 16; off > 0; off >>= 1) v += __shfl_down_sync(FULL, v, off);
            v = __shfl_sync(FULL, v, 0);
            float ex = expf(v - emax);
            lsum += ex;
            r0 = fmaf(ex, x0, r0);
            r1 = fmaf(ex, x1, r1);
        }
        if (lane == 0) red[w] = lsum;
        rpart[w][lane] = r0;
        rpart[w][32 + lane] = r1;
        __syncthreads();
        if (tid == 0) {
            float ssum = 0.0f;
#pragma unroll
            for (int i = 0; i < 8; i++) ssum += red[i];
            denom_s = ssum;
        }
        __syncthreads();
        if (tid < 64) {
            float rv = 0.0f;
#pragma unroll
            for (int i = 0; i < 8; i++) rv += rpart[i][tid];
            q[64 + tid] = rv / (denom_s + 1e-16f);
            q[tid] = hl[tid];
        }
        __syncthreads();
    }

    if (tid < 64) {
        float acc = lin1_b[tid];
        const float* wr = lin1_w + tid * 128;
#pragma unroll 8
        for (int k = 0; k < 128; k++) acc = fmaf(q[k], wr[k], acc);
        z[tid] = fmaxf(acc, 0.0f);
    }
    __syncthreads();
    if (tid < 12) {
        float acc = lin2_b[tid];
        const float* wr = lin2_w + tid * 64;
#pragma unroll
        for (int d = 0; d < 64; d++) acc = fmaf(z[d], wr[d], acc);
        out[b * 12 + tid] = acc;
    }
}

// ---------------- launch ----------------
extern "C" void kernel_launch(void* const* d_in, const int* in_sizes, int n_in,
                              void* d_out, int out_size) {
    const float* x         = (const float*)d_in[0];
    const float* edge_attr = (const float*)d_in[1];
    const int*   edge_index= (const int*)  d_in[2];
    const int*   batch     = (const int*)  d_in[3];
    const float* lin0_w    = (const float*)d_in[4];
    const float* lin0_b    = (const float*)d_in[5];
    const float* en_w1     = (const float*)d_in[6];
    const float* en_b1     = (const float*)d_in[7];
    const float* en_w2     = (const float*)d_in[8];
    const float* en_b2     = (const float*)d_in[9];
    const float* conv_b    = (const float*)d_in[10];
    const float* gru_w_ih  = (const float*)d_in[11];
    const float* gru_w_hh  = (const float*)d_in[12];
    const float* gru_b_ih  = (const float*)d_in[13];
    const float* gru_b_hh  = (const float*)d_in[14];
    const float* lstm_w_ih = (const float*)d_in[15];
    const float* lstm_w_hh = (const float*)d_in[16];
    const float* lstm_b_ih = (const float*)d_in[17];
    const float* lstm_b_hh = (const float*)d_in[18];
    const float* lin1_w    = (const float*)d_in[19];
    const float* lin1_b    = (const float*)d_in[20];
    const float* lin2_w    = (const float*)d_in[21];
    const float* lin2_b    = (const float*)d_in[22];
    float* out = (float*)d_out;

    const int gemm_smem = 2 * 128 * SPAD * (int)sizeof(__nv_bfloat16);  // 69632
    cudaFuncSetAttribute(gemm_ew_mma, cudaFuncAttributeMaxDynamicSharedMemorySize,
                         gemm_smem);
    cudaFuncSetAttribute(gemm_gates_mma, cudaFuncAttributeMaxDynamicSharedMemorySize,
                         gemm_smem);
    cudaFuncSetAttribute(csr_kernel, cudaFuncAttributeMaxDynamicSharedMemorySize,
                         Nn * (int)sizeof(int));

    prep_a_kernel<<<(PA_TOT + 255) / 256, 256>>>(x, lin0_w, lin0_b, batch);
    prep_b1_kernel<<<(PB1_TOT + 255) / 256, 256>>>(en_w2, edge_index,
                                                   gru_w_ih, gru_w_hh);
    csr_kernel<<<1, 1024, Nn * sizeof(int)>>>(edge_index);
    prep_b2_kernel<<<(PB2_TOT + 255) / 256, 256>>>(edge_attr, en_w1, en_b1, edge_index);

    dim3 gemm_grid(DDf / 128, (Ee + 127) / 128);
    gemm_ew_mma<<<gemm_grid, 256, gemm_smem>>>(en_b2);

    dim3 gates_grid(3, (Nn + 127) / 128);
    for (int s = 0; s < NSTEPS; s++) {
        gather_x_kernel<<<(Ee * 8 + 255) / 256, 256>>>();
        msgagg_kernel<<<(Nn + 7) / 8, 256>>>(conv_b);
        gemm_gates_mma<<<gates_grid, 256, gemm_smem>>>();
        gru_epi_kernel<<<(Nn * 64 + 255) / 256, 256>>>(gru_b_ih, gru_b_hh);
    }

    set2set_kernel<<<Bb, 256>>>(lstm_w_ih, lstm_w_hh, lstm_b_ih, lstm_b_hh,
                                lin1_w, lin1_b, lin2_w, lin2_b, out);
}